// round 13
// baseline (speedup 1.0000x reference)
#include <cuda_runtime.h>
#include <cuda_bf16.h>
#include <cuda_fp16.h>
#include <cstdint>
#include <cstddef>

// ---------------------------------------------------------------------------
// SageLayer pipeline v12: R8 split structure + fp16 Y storage + ssq partials.
//   out[b] = normalize(leaky( X @ A^T + c ))[nodes_idx]
//   X[u] = [ emb[uid[u]] | mean_k emb[adj[u,k]] | mean_k emb[dis[u,k]] ]
//   Weights folded to one 384x384 fp16 matrix inside the gather launch.
//   GEMM: fp16 mma.sync, K=384 (validated R5-R11). Y stored fp16; row
//   sum-of-squares (fp32, deterministic partials) from the GEMM epilogue.
// ---------------------------------------------------------------------------

#define U_NODES 16384
#define K_NEIGH 32
#define D_IN    128
#define D_OUT   384
#define B_OUT   32768
#define FOLD_BLOCKS 384

// ---- device scratch ----
__device__ __align__(16) float g_c[384];
__device__ __align__(16) __half g_X[(size_t)U_NODES * 384];
__device__ __align__(16) __half g_B[384 * 384];             // folded A[n][k]
__device__ __align__(16) __half g_Yh[(size_t)U_NODES * 384]; // fp16 Y
__device__ __align__(16) float g_ssq[(size_t)U_NODES * 6];   // per-(row, nb*2+wn)

// ---- helpers ----
__device__ __forceinline__ uint32_t smem_u32(const void* p) {
    uint32_t a;
    asm("{ .reg .u64 t; cvta.to.shared.u64 t, %1; cvt.u32.u64 %0, t; }"
        : "=r"(a) : "l"(p));
    return a;
}
__device__ __forceinline__ void cp_async16(uint32_t dst, const void* src) {
    asm volatile("cp.async.cg.shared.global [%0], [%1], 16;"
                 :: "r"(dst), "l"(src) : "memory");
}
__device__ __forceinline__ void cp_commit() {
    asm volatile("cp.async.commit_group;" ::: "memory");
}
template <int N>
__device__ __forceinline__ void cp_wait() {
    asm volatile("cp.async.wait_group %0;" :: "n"(N) : "memory");
}
__device__ __forceinline__ void ldsm_x4(uint32_t& r0, uint32_t& r1,
                                        uint32_t& r2, uint32_t& r3, uint32_t a) {
    asm volatile("ldmatrix.sync.aligned.m8n8.x4.shared.b16 {%0,%1,%2,%3}, [%4];"
                 : "=r"(r0), "=r"(r1), "=r"(r2), "=r"(r3) : "r"(a));
}
__device__ __forceinline__ void mma16816(float& c0, float& c1, float& c2, float& c3,
                                         uint32_t a0, uint32_t a1, uint32_t a2, uint32_t a3,
                                         uint32_t b0, uint32_t b1) {
    asm volatile(
        "mma.sync.aligned.m16n8k16.row.col.f32.f16.f16.f32 "
        "{%0,%1,%2,%3}, {%4,%5,%6,%7}, {%8,%9}, {%0,%1,%2,%3};"
        : "+f"(c0), "+f"(c1), "+f"(c2), "+f"(c3)
        : "r"(a0), "r"(a1), "r"(a2), "r"(a3), "r"(b0), "r"(b1));
}
__device__ __forceinline__ uint32_t pack_half2_u32(float a, float b) {
    __half2 h = __floats2half2_rn(a, b);
    return *(uint32_t*)&h;
}

// ---------------------------------------------------------------------------
// fused fold + gather kernel (R8-validated)
//   blocks [0, 384):        fold output-row n of B and c
//   blocks [384, 384+16384): gather+mean node u = blockIdx.x - 384
// ---------------------------------------------------------------------------
__global__ void __launch_bounds__(128) fold_gather_kernel(
        const float* __restrict__ emb,
        const int* __restrict__ uid,
        const int* __restrict__ adj,
        const int* __restrict__ dis,
        const float* __restrict__ Wa_adj,
        const float* __restrict__ ba_adj,
        const float* __restrict__ Wa_dis,
        const float* __restrict__ ba_dis,
        const float* __restrict__ W_self,
        const float* __restrict__ W_adj,
        const float* __restrict__ W_dis,
        const float* __restrict__ WC,
        const float* __restrict__ bWC,
        const float* __restrict__ bias) {
    const int t = threadIdx.x;

    if (blockIdx.x < FOLD_BLOCKS) {
        // ---------------- fold: B[n][:] (fp16) and c[n] ---------------------
        const int n = blockIdx.x;
        __shared__ float wcn[384];
        __shared__ float tbuf[128];
        __shared__ float red[128];

        wcn[t]       = WC[n * 384 + t];
        wcn[t + 128] = WC[n * 384 + 128 + t];
        wcn[t + 256] = WC[n * 384 + 256 + t];
        __syncthreads();

        {
            float a = 0.f;
#pragma unroll 8
            for (int e = 0; e < 128; e++)
                a += wcn[e] * W_self[e * 128 + t];
            g_B[n * 384 + t] = __float2half_rn(a);
        }

        float csum = 0.f;

        {
            float tv = 0.f;
#pragma unroll 8
            for (int g = 0; g < 128; g++)
                tv += wcn[128 + g] * W_adj[g * 128 + t];
            tbuf[t] = tv;
            __syncthreads();
            float a2 = 0.f;
#pragma unroll 8
            for (int e = 0; e < 128; e++)
                a2 += tbuf[e] * Wa_adj[e * 128 + t];
            g_B[n * 384 + 128 + t] = __float2half_rn(a2);
            red[t] = tv * ba_adj[t];
            __syncthreads();
#pragma unroll
            for (int s = 64; s > 0; s >>= 1) {
                if (t < s) red[t] += red[t + s];
                __syncthreads();
            }
            csum += red[0];
            __syncthreads();
        }

        {
            float tv = 0.f;
#pragma unroll 8
            for (int g = 0; g < 128; g++)
                tv += wcn[256 + g] * W_dis[g * 128 + t];
            tbuf[t] = tv;
            __syncthreads();
            float a2 = 0.f;
#pragma unroll 8
            for (int e = 0; e < 128; e++)
                a2 += tbuf[e] * Wa_dis[e * 128 + t];
            g_B[n * 384 + 256 + t] = __float2half_rn(a2);
            red[t] = tv * ba_dis[t];
            __syncthreads();
#pragma unroll
            for (int s = 64; s > 0; s >>= 1) {
                if (t < s) red[t] += red[t + s];
                __syncthreads();
            }
            csum += red[0];
        }

        if (t == 0) g_c[n] = csum + bWC[n] + bias[n];
        return;
    }

    // ---------------- gather + mean (float4 per lane) -----------------------
    const int u = blockIdx.x - FOLD_BLOCKS;
    const int lane = t & 31;
    const int w = t >> 5;

    __shared__ int sa[K_NEIGH];
    __shared__ int sd[K_NEIGH];
    __shared__ int sself;
    __shared__ float4 part[2][4][32];

    if (t < 32)       sa[t]      = adj[(size_t)u * K_NEIGH + t];
    else if (t < 64)  sd[t - 32] = dis[(size_t)u * K_NEIGH + (t - 32)];
    else if (t == 64) sself      = uid[u];
    __syncthreads();

    const float4* e4 = (const float4*)emb;   // 32 float4 per 128-dim row

    float4 vself;
    if (w == 2) vself = e4[(size_t)sself * 32 + lane];

    float4 aa = make_float4(0.f, 0.f, 0.f, 0.f);
    float4 ad = make_float4(0.f, 0.f, 0.f, 0.f);
#pragma unroll
    for (int j = 0; j < 8; j++) {
        const int k = w * 8 + j;
        float4 va = e4[(size_t)sa[k] * 32 + lane];
        float4 vd = e4[(size_t)sd[k] * 32 + lane];
        aa.x += va.x; aa.y += va.y; aa.z += va.z; aa.w += va.w;
        ad.x += vd.x; ad.y += vd.y; ad.z += vd.z; ad.w += vd.w;
    }
    part[0][w][lane] = aa;
    part[1][w][lane] = ad;

    if (w == 2) {
        uint2 pk;
        pk.x = pack_half2_u32(vself.x, vself.y);
        pk.y = pack_half2_u32(vself.z, vself.w);
        *(uint2*)&g_X[(size_t)u * 384 + lane * 4] = pk;
    }
    __syncthreads();

    if (t < 64) {
        const int which = t >> 5;       // 0=adj, 1=dis
        const int l = t & 31;
        float4 s0 = part[which][0][l];
        float4 s1 = part[which][1][l];
        float4 s2 = part[which][2][l];
        float4 s3 = part[which][3][l];
        const float sc = 1.0f / 32.0f;
        float x0 = (s0.x + s1.x + s2.x + s3.x) * sc;
        float x1 = (s0.y + s1.y + s2.y + s3.y) * sc;
        float x2 = (s0.z + s1.z + s2.z + s3.z) * sc;
        float x3 = (s0.w + s1.w + s2.w + s3.w) * sc;
        uint2 pk;
        pk.x = pack_half2_u32(x0, x1);
        pk.y = pack_half2_u32(x2, x3);
        *(uint2*)&g_X[(size_t)u * 384 + 128 + which * 128 + l * 4] = pk;
    }
}

// ---------------------------------------------------------------------------
// GEMM: Y = leaky( X[16384,384] @ A^T + c ) via fp16 mma.sync
// K = 384, k-chunk 64, 6 iters. CTA 128x128, 8 warps (4m x 2n), warp 32x64.
// 3-stage cp.async pipeline (R8 ordering). Y stored fp16; ssq partials fp32.
// ---------------------------------------------------------------------------
#define KCH      64
#define ROWB     144
#define STG_OP   (128 * ROWB)
#define STG_B    (2 * STG_OP)
#define NSTG     3
#define GSM_TOT  (NSTG * STG_B)          // 110592 B

__global__ __launch_bounds__(256, 2) void gemm_hmma_kernel() {
    extern __shared__ char gsm[];
    const uint32_t base = smem_u32(gsm);

    const int t = threadIdx.x;
    const int lane = t & 31;
    const int wid = t >> 5;
    const int wm = wid & 3;
    const int wn = wid >> 2;
    const int nb = blockIdx.x;
    const int n0 = nb * 128;
    const int m0 = blockIdx.y * 128;

    const uint32_t a_lm = (uint32_t)((lane & 15) * ROWB + (lane >> 4) * 16);
    const uint32_t b_lm = (uint32_t)(((lane & 7) + ((lane >> 4) << 3)) * ROWB
                                     + (((lane >> 3) & 1) << 4));

    float acc[2][8][4];
#pragma unroll
    for (int i = 0; i < 2; i++)
#pragma unroll
        for (int j = 0; j < 8; j++)
#pragma unroll
            for (int q = 0; q < 4; q++) acc[i][j][q] = 0.f;

    auto load_iter = [&](int it, int s) {
        const int kc = it * KCH;
        const uint32_t sb = base + (uint32_t)(s * STG_B);
#pragma unroll
        for (int j = 0; j < 4; j++) {
            const int q = t + j * 256;
            const int r = q >> 3;
            const int ch = q & 7;
            cp_async16(sb + (uint32_t)(r * ROWB + ch * 16),
                       g_X + (size_t)(m0 + r) * 384 + kc + ch * 8);
            cp_async16(sb + (uint32_t)(STG_OP + r * ROWB + ch * 16),
                       g_B + (size_t)(n0 + r) * 384 + kc + ch * 8);
        }
        cp_commit();
    };

    load_iter(0, 0);
    load_iter(1, 1);

    for (int it = 0; it < 6; it++) {
        if (it == 5) cp_wait<0>(); else cp_wait<1>();
        __syncthreads();

        const int s = it % NSTG;
        const uint32_t a_tile = base + (uint32_t)(s * STG_B + wm * 32 * ROWB) + a_lm;
        const uint32_t b_tile = base + (uint32_t)(s * STG_B + STG_OP + wn * 64 * ROWB) + b_lm;

#pragma unroll
        for (int ks = 0; ks < 4; ks++) {
            uint32_t af[2][4];
            uint32_t bf_[4][4];
#pragma unroll
            for (int mi = 0; mi < 2; mi++)
                ldsm_x4(af[mi][0], af[mi][1], af[mi][2], af[mi][3],
                        a_tile + (uint32_t)(mi * 16 * ROWB + ks * 32));
#pragma unroll
            for (int bj = 0; bj < 4; bj++)
                ldsm_x4(bf_[bj][0], bf_[bj][1], bf_[bj][2], bf_[bj][3],
                        b_tile + (uint32_t)(bj * 16 * ROWB + ks * 32));
#pragma unroll
            for (int mi = 0; mi < 2; mi++)
#pragma unroll
                for (int nj = 0; nj < 8; nj++)
                    mma16816(acc[mi][nj][0], acc[mi][nj][1],
                             acc[mi][nj][2], acc[mi][nj][3],
                             af[mi][0], af[mi][1], af[mi][2], af[mi][3],
                             bf_[nj >> 1][(nj & 1) * 2],
                             bf_[nj >> 1][(nj & 1) * 2 + 1]);
        }

        if (it + 2 < 6) load_iter(it + 2, (it + 2) % NSTG);
    }

    // ---- epilogue: += c, leaky relu, store fp16 Y + fp32 ssq partials ----
    float cv[8][2];
#pragma unroll
    for (int nj = 0; nj < 8; nj++) {
        const int col = n0 + wn * 64 + nj * 8 + (lane & 3) * 2;
        cv[nj][0] = g_c[col];
        cv[nj][1] = g_c[col + 1];
    }
#pragma unroll
    for (int mi = 0; mi < 2; mi++) {
        const int row = m0 + wm * 32 + mi * 16 + (lane >> 2);
        float ssq_r0 = 0.f, ssq_r8 = 0.f;
#pragma unroll
        for (int nj = 0; nj < 8; nj++) {
            const int col = n0 + wn * 64 + nj * 8 + (lane & 3) * 2;
            float y0 = acc[mi][nj][0] + cv[nj][0];
            float y1 = acc[mi][nj][1] + cv[nj][1];
            float y2 = acc[mi][nj][2] + cv[nj][0];
            float y3 = acc[mi][nj][3] + cv[nj][1];
            y0 = (y0 > 0.f) ? y0 : 0.2f * y0;
            y1 = (y1 > 0.f) ? y1 : 0.2f * y1;
            y2 = (y2 > 0.f) ? y2 : 0.2f * y2;
            y3 = (y3 > 0.f) ? y3 : 0.2f * y3;
            ssq_r0 += y0 * y0 + y1 * y1;
            ssq_r8 += y2 * y2 + y3 * y3;
            *(uint32_t*)&g_Yh[(size_t)row * 384 + col]       = pack_half2_u32(y0, y1);
            *(uint32_t*)&g_Yh[(size_t)(row + 8) * 384 + col] = pack_half2_u32(y2, y3);
        }
        ssq_r0 += __shfl_xor_sync(0xffffffffu, ssq_r0, 1);
        ssq_r0 += __shfl_xor_sync(0xffffffffu, ssq_r0, 2);
        ssq_r8 += __shfl_xor_sync(0xffffffffu, ssq_r8, 1);
        ssq_r8 += __shfl_xor_sync(0xffffffffu, ssq_r8, 2);
        if ((lane & 3) == 0) {
            g_ssq[(size_t)row * 6 + nb * 2 + wn]       = ssq_r0;
            g_ssq[(size_t)(row + 8) * 6 + nb * 2 + wn] = ssq_r8;
        }
    }
}

// ---------------------------------------------------------------------------
// norm_gather: out[b] = Yh[u] / max(sqrt(ssq[u]), 1e-12), u = nodes_idx[b]
// One warp per output row; lane l owns cols [l*12, l*12+12).
// ---------------------------------------------------------------------------
__global__ void norm_gather_kernel(const int* __restrict__ nodes_idx,
                                   float* __restrict__ out) {
    __shared__ int sidx[8];
    const int w = threadIdx.x >> 5;
    const int l = threadIdx.x & 31;
    if (threadIdx.x < 8) sidx[threadIdx.x] = nodes_idx[blockIdx.x * 8 + threadIdx.x];
    __syncthreads();

    const int b = blockIdx.x * 8 + w;
    const int u = sidx[w];

    const float* sp = g_ssq + (size_t)u * 6;
    const float s = ((sp[0] + sp[1]) + (sp[2] + sp[3])) + (sp[4] + sp[5]);
    const float inv = 1.0f / fmaxf(sqrtf(s), 1e-12f);

    const __half* yr = g_Yh + (size_t)u * 384 + l * 12;
    uint2 h0 = *(const uint2*)(yr);
    uint2 h1 = *(const uint2*)(yr + 4);
    uint2 h2 = *(const uint2*)(yr + 8);

    float* o = out + (size_t)b * 384 + l * 12;
    float2 p;
    float4 v;
    p = __half22float2(*(__half2*)&h0.x); v.x = p.x * inv; v.y = p.y * inv;
    p = __half22float2(*(__half2*)&h0.y); v.z = p.x * inv; v.w = p.y * inv;
    *(float4*)(o) = v;
    p = __half22float2(*(__half2*)&h1.x); v.x = p.x * inv; v.y = p.y * inv;
    p = __half22float2(*(__half2*)&h1.y); v.z = p.x * inv; v.w = p.y * inv;
    *(float4*)(o + 4) = v;
    p = __half22float2(*(__half2*)&h2.x); v.x = p.x * inv; v.y = p.y * inv;
    p = __half22float2(*(__half2*)&h2.y); v.z = p.x * inv; v.w = p.y * inv;
    *(float4*)(o + 8) = v;
}

// ---------------------------------------------------------------------------
extern "C" void kernel_launch(void* const* d_in, const int* in_sizes, int n_in,
                              void* d_out, int out_size) {
    const float* emb    = (const float*)d_in[0];
    const float* Wa_adj = (const float*)d_in[1];
    const float* ba_adj = (const float*)d_in[2];
    const float* Wa_dis = (const float*)d_in[3];
    const float* ba_dis = (const float*)d_in[4];
    const float* W_self = (const float*)d_in[5];
    const float* W_adj  = (const float*)d_in[6];
    const float* W_dis  = (const float*)d_in[7];
    const float* WC     = (const float*)d_in[8];
    const float* bWC    = (const float*)d_in[9];
    const float* bias   = (const float*)d_in[10];
    const int* uid      = (const int*)d_in[11];
    const int* adj      = (const int*)d_in[12];
    const int* dis      = (const int*)d_in[13];
    const int* nidx     = (const int*)d_in[14];
    float* out          = (float*)d_out;

    cudaFuncSetAttribute(gemm_hmma_kernel,
                         cudaFuncAttributeMaxDynamicSharedMemorySize, GSM_TOT);

    fold_gather_kernel<<<FOLD_BLOCKS + U_NODES, 128>>>(
        emb, uid, adj, dis,
        Wa_adj, ba_adj, Wa_dis, ba_dis,
        W_self, W_adj, W_dis, WC, bWC, bias);
    gemm_hmma_kernel<<<dim3(3, 128), 256, GSM_TOT>>>();
    norm_gather_kernel<<<B_OUT / 8, 256>>>(nidx, out);
}

// round 14
// speedup vs baseline: 1.0327x; 1.0327x over previous
#include <cuda_runtime.h>
#include <cuda_bf16.h>
#include <cuda_fp16.h>
#include <cstdint>
#include <cstddef>

// ---------------------------------------------------------------------------
// SageLayer pipeline v13: R8 structure (validated 124.5us) with a 512-thread
// 16-warp GEMM (4m x 4n warp grid, 32x32 warp tile) for 2x warp-parallelism
// at the same smem footprint / CTA occupancy.
//   out[b] = normalize(leaky( X @ A^T + c ))[nodes_idx]
//   X[u] = [ emb[uid[u]] | mean_k emb[adj[u,k]] | mean_k emb[dis[u,k]] ]
//   Weights folded to one 384x384 fp16 matrix inside the gather launch.
// ---------------------------------------------------------------------------

#define U_NODES 16384
#define K_NEIGH 32
#define D_IN    128
#define D_OUT   384
#define B_OUT   32768
#define FOLD_BLOCKS 384

// ---- device scratch ----
__device__ __align__(16) float g_c[384];
__device__ __align__(16) __half g_X[(size_t)U_NODES * 384];
__device__ __align__(16) __half g_B[384 * 384];            // folded A[n][k]
__device__ __align__(16) float g_Y[(size_t)U_NODES * 384];

// ---- helpers ----
__device__ __forceinline__ uint32_t smem_u32(const void* p) {
    uint32_t a;
    asm("{ .reg .u64 t; cvta.to.shared.u64 t, %1; cvt.u32.u64 %0, t; }"
        : "=r"(a) : "l"(p));
    return a;
}
__device__ __forceinline__ void cp_async16(uint32_t dst, const void* src) {
    asm volatile("cp.async.cg.shared.global [%0], [%1], 16;"
                 :: "r"(dst), "l"(src) : "memory");
}
__device__ __forceinline__ void cp_commit() {
    asm volatile("cp.async.commit_group;" ::: "memory");
}
template <int N>
__device__ __forceinline__ void cp_wait() {
    asm volatile("cp.async.wait_group %0;" :: "n"(N) : "memory");
}
__device__ __forceinline__ void ldsm_x4(uint32_t& r0, uint32_t& r1,
                                        uint32_t& r2, uint32_t& r3, uint32_t a) {
    asm volatile("ldmatrix.sync.aligned.m8n8.x4.shared.b16 {%0,%1,%2,%3}, [%4];"
                 : "=r"(r0), "=r"(r1), "=r"(r2), "=r"(r3) : "r"(a));
}
__device__ __forceinline__ void mma16816(float& c0, float& c1, float& c2, float& c3,
                                         uint32_t a0, uint32_t a1, uint32_t a2, uint32_t a3,
                                         uint32_t b0, uint32_t b1) {
    asm volatile(
        "mma.sync.aligned.m16n8k16.row.col.f32.f16.f16.f32 "
        "{%0,%1,%2,%3}, {%4,%5,%6,%7}, {%8,%9}, {%0,%1,%2,%3};"
        : "+f"(c0), "+f"(c1), "+f"(c2), "+f"(c3)
        : "r"(a0), "r"(a1), "r"(a2), "r"(a3), "r"(b0), "r"(b1));
}
__device__ __forceinline__ uint32_t pack_half2_u32(float a, float b) {
    __half2 h = __floats2half2_rn(a, b);
    return *(uint32_t*)&h;
}

// ---------------------------------------------------------------------------
// fused fold + gather kernel (R8-validated, unchanged)
//   blocks [0, 384):        fold output-row n of B and c
//   blocks [384, 384+16384): gather+mean node u = blockIdx.x - 384
// ---------------------------------------------------------------------------
__global__ void __launch_bounds__(128) fold_gather_kernel(
        const float* __restrict__ emb,
        const int* __restrict__ uid,
        const int* __restrict__ adj,
        const int* __restrict__ dis,
        const float* __restrict__ Wa_adj,
        const float* __restrict__ ba_adj,
        const float* __restrict__ Wa_dis,
        const float* __restrict__ ba_dis,
        const float* __restrict__ W_self,
        const float* __restrict__ W_adj,
        const float* __restrict__ W_dis,
        const float* __restrict__ WC,
        const float* __restrict__ bWC,
        const float* __restrict__ bias) {
    const int t = threadIdx.x;

    if (blockIdx.x < FOLD_BLOCKS) {
        const int n = blockIdx.x;
        __shared__ float wcn[384];
        __shared__ float tbuf[128];
        __shared__ float red[128];

        wcn[t]       = WC[n * 384 + t];
        wcn[t + 128] = WC[n * 384 + 128 + t];
        wcn[t + 256] = WC[n * 384 + 256 + t];
        __syncthreads();

        {
            float a = 0.f;
#pragma unroll 8
            for (int e = 0; e < 128; e++)
                a += wcn[e] * W_self[e * 128 + t];
            g_B[n * 384 + t] = __float2half_rn(a);
        }

        float csum = 0.f;

        {
            float tv = 0.f;
#pragma unroll 8
            for (int g = 0; g < 128; g++)
                tv += wcn[128 + g] * W_adj[g * 128 + t];
            tbuf[t] = tv;
            __syncthreads();
            float a2 = 0.f;
#pragma unroll 8
            for (int e = 0; e < 128; e++)
                a2 += tbuf[e] * Wa_adj[e * 128 + t];
            g_B[n * 384 + 128 + t] = __float2half_rn(a2);
            red[t] = tv * ba_adj[t];
            __syncthreads();
#pragma unroll
            for (int s = 64; s > 0; s >>= 1) {
                if (t < s) red[t] += red[t + s];
                __syncthreads();
            }
            csum += red[0];
            __syncthreads();
        }

        {
            float tv = 0.f;
#pragma unroll 8
            for (int g = 0; g < 128; g++)
                tv += wcn[256 + g] * W_dis[g * 128 + t];
            tbuf[t] = tv;
            __syncthreads();
            float a2 = 0.f;
#pragma unroll 8
            for (int e = 0; e < 128; e++)
                a2 += tbuf[e] * Wa_dis[e * 128 + t];
            g_B[n * 384 + 256 + t] = __float2half_rn(a2);
            red[t] = tv * ba_dis[t];
            __syncthreads();
#pragma unroll
            for (int s = 64; s > 0; s >>= 1) {
                if (t < s) red[t] += red[t + s];
                __syncthreads();
            }
            csum += red[0];
        }

        if (t == 0) g_c[n] = csum + bWC[n] + bias[n];
        return;
    }

    // ---------------- gather + mean (float4 per lane) -----------------------
    const int u = blockIdx.x - FOLD_BLOCKS;
    const int lane = t & 31;
    const int w = t >> 5;

    __shared__ int sa[K_NEIGH];
    __shared__ int sd[K_NEIGH];
    __shared__ int sself;
    __shared__ float4 part[2][4][32];

    if (t < 32)       sa[t]      = adj[(size_t)u * K_NEIGH + t];
    else if (t < 64)  sd[t - 32] = dis[(size_t)u * K_NEIGH + (t - 32)];
    else if (t == 64) sself      = uid[u];
    __syncthreads();

    const float4* e4 = (const float4*)emb;   // 32 float4 per 128-dim row

    float4 vself;
    if (w == 2) vself = e4[(size_t)sself * 32 + lane];

    float4 aa = make_float4(0.f, 0.f, 0.f, 0.f);
    float4 ad = make_float4(0.f, 0.f, 0.f, 0.f);
#pragma unroll
    for (int j = 0; j < 8; j++) {
        const int k = w * 8 + j;
        float4 va = e4[(size_t)sa[k] * 32 + lane];
        float4 vd = e4[(size_t)sd[k] * 32 + lane];
        aa.x += va.x; aa.y += va.y; aa.z += va.z; aa.w += va.w;
        ad.x += vd.x; ad.y += vd.y; ad.z += vd.z; ad.w += vd.w;
    }
    part[0][w][lane] = aa;
    part[1][w][lane] = ad;

    if (w == 2) {
        uint2 pk;
        pk.x = pack_half2_u32(vself.x, vself.y);
        pk.y = pack_half2_u32(vself.z, vself.w);
        *(uint2*)&g_X[(size_t)u * 384 + lane * 4] = pk;
    }
    __syncthreads();

    if (t < 64) {
        const int which = t >> 5;       // 0=adj, 1=dis
        const int l = t & 31;
        float4 s0 = part[which][0][l];
        float4 s1 = part[which][1][l];
        float4 s2 = part[which][2][l];
        float4 s3 = part[which][3][l];
        const float sc = 1.0f / 32.0f;
        float x0 = (s0.x + s1.x + s2.x + s3.x) * sc;
        float x1 = (s0.y + s1.y + s2.y + s3.y) * sc;
        float x2 = (s0.z + s1.z + s2.z + s3.z) * sc;
        float x3 = (s0.w + s1.w + s2.w + s3.w) * sc;
        uint2 pk;
        pk.x = pack_half2_u32(x0, x1);
        pk.y = pack_half2_u32(x2, x3);
        *(uint2*)&g_X[(size_t)u * 384 + 128 + which * 128 + l * 4] = pk;
    }
}

// ---------------------------------------------------------------------------
// GEMM: Y = leaky( X[16384,384] @ A^T + c ) via fp16 mma.sync
// K=384, k-chunk 64, 6 iters. CTA 128x128, **512 threads, 16 warps (4m x 4n),
// warp tile 32x32** — 2x warp-parallelism at the same smem/occupancy.
// 3-stage cp.async pipeline, one __syncthreads per iter.
// smem rows padded to 144 B (conflict-free ldmatrix).
// ---------------------------------------------------------------------------
#define KCH      64
#define ROWB     144
#define STG_OP   (128 * ROWB)
#define STG_B    (2 * STG_OP)
#define NSTG     3
#define GSM_TOT  (NSTG * STG_B)          // 110592 B

__global__ __launch_bounds__(512, 2) void gemm_hmma_kernel() {
    extern __shared__ char gsm[];
    const uint32_t base = smem_u32(gsm);

    const int t = threadIdx.x;
    const int lane = t & 31;
    const int wid = t >> 5;          // 0..15
    const int wm = wid & 3;          // 4 m-warps x 32 rows
    const int wn = wid >> 2;         // 4 n-warps x 32 cols
    const int n0 = blockIdx.x * 128;
    const int m0 = blockIdx.y * 128;

    const uint32_t a_lm = (uint32_t)((lane & 15) * ROWB + (lane >> 4) * 16);
    const uint32_t b_lm = (uint32_t)(((lane & 7) + ((lane >> 4) << 3)) * ROWB
                                     + (((lane >> 3) & 1) << 4));

    float acc[2][4][4];
#pragma unroll
    for (int i = 0; i < 2; i++)
#pragma unroll
        for (int j = 0; j < 4; j++)
#pragma unroll
            for (int q = 0; q < 4; q++) acc[i][j][q] = 0.f;

    auto load_iter = [&](int it, int s) {
        const int kc = it * KCH;
        const uint32_t sb = base + (uint32_t)(s * STG_B);
#pragma unroll
        for (int j = 0; j < 2; j++) {
            const int q = t + j * 512;          // 0..1023
            const int r = q >> 3;               // row 0..127
            const int ch = q & 7;               // 16B chunk (8 per 128B row)
            cp_async16(sb + (uint32_t)(r * ROWB + ch * 16),
                       g_X + (size_t)(m0 + r) * 384 + kc + ch * 8);
            cp_async16(sb + (uint32_t)(STG_OP + r * ROWB + ch * 16),
                       g_B + (size_t)(n0 + r) * 384 + kc + ch * 8);
        }
        cp_commit();
    };

    load_iter(0, 0);
    load_iter(1, 1);

    for (int it = 0; it < 6; it++) {
        if (it == 5) cp_wait<0>(); else cp_wait<1>();
        __syncthreads();

        const int s = it % NSTG;
        const uint32_t a_tile = base + (uint32_t)(s * STG_B + wm * 32 * ROWB) + a_lm;
        const uint32_t b_tile = base + (uint32_t)(s * STG_B + STG_OP + wn * 32 * ROWB) + b_lm;

#pragma unroll
        for (int ks = 0; ks < 4; ks++) {
            uint32_t af[2][4];
            uint32_t bf_[2][4];
#pragma unroll
            for (int mi = 0; mi < 2; mi++)
                ldsm_x4(af[mi][0], af[mi][1], af[mi][2], af[mi][3],
                        a_tile + (uint32_t)(mi * 16 * ROWB + ks * 32));
#pragma unroll
            for (int bj = 0; bj < 2; bj++)
                ldsm_x4(bf_[bj][0], bf_[bj][1], bf_[bj][2], bf_[bj][3],
                        b_tile + (uint32_t)(bj * 16 * ROWB + ks * 32));
#pragma unroll
            for (int mi = 0; mi < 2; mi++)
#pragma unroll
                for (int nj = 0; nj < 4; nj++)
                    mma16816(acc[mi][nj][0], acc[mi][nj][1],
                             acc[mi][nj][2], acc[mi][nj][3],
                             af[mi][0], af[mi][1], af[mi][2], af[mi][3],
                             bf_[nj >> 1][(nj & 1) * 2],
                             bf_[nj >> 1][(nj & 1) * 2 + 1]);
        }

        if (it + 2 < 6) load_iter(it + 2, (it + 2) % NSTG);
    }

    // ---- epilogue: += c, leaky relu, store to g_Y ----
    float cv[4][2];
#pragma unroll
    for (int nj = 0; nj < 4; nj++) {
        const int col = n0 + wn * 32 + nj * 8 + (lane & 3) * 2;
        cv[nj][0] = g_c[col];
        cv[nj][1] = g_c[col + 1];
    }
#pragma unroll
    for (int mi = 0; mi < 2; mi++) {
        const int row = m0 + wm * 32 + mi * 16 + (lane >> 2);
#pragma unroll
        for (int nj = 0; nj < 4; nj++) {
            const int col = n0 + wn * 32 + nj * 8 + (lane & 3) * 2;
            float y0 = acc[mi][nj][0] + cv[nj][0];
            float y1 = acc[mi][nj][1] + cv[nj][1];
            float y2 = acc[mi][nj][2] + cv[nj][0];
            float y3 = acc[mi][nj][3] + cv[nj][1];
            y0 = (y0 > 0.f) ? y0 : 0.2f * y0;
            y1 = (y1 > 0.f) ? y1 : 0.2f * y1;
            y2 = (y2 > 0.f) ? y2 : 0.2f * y2;
            y3 = (y3 > 0.f) ? y3 : 0.2f * y3;
            *(float2*)&g_Y[(size_t)row * 384 + col]       = make_float2(y0, y1);
            *(float2*)&g_Y[(size_t)(row + 8) * 384 + col] = make_float2(y2, y3);
        }
    }
}

// ---------------------------------------------------------------------------
// norm_gather: out[b] = normalize(Y[nodes_idx[b]])  (R8-validated)
// ---------------------------------------------------------------------------
__global__ void norm_gather_kernel(const int* __restrict__ nodes_idx,
                                   float* __restrict__ out) {
    __shared__ int sidx[8];
    const int w = threadIdx.x >> 5;
    const int l = threadIdx.x & 31;
    if (threadIdx.x < 8) sidx[threadIdx.x] = nodes_idx[blockIdx.x * 8 + threadIdx.x];
    __syncthreads();

    const int b = blockIdx.x * 8 + w;
    const int u = sidx[w];

    const float4* yr = (const float4*)(g_Y + (size_t)u * 384);
    float4 v0 = yr[l];
    float4 v1 = yr[l + 32];
    float4 v2 = yr[l + 64];

    float s = v0.x * v0.x + v0.y * v0.y + v0.z * v0.z + v0.w * v0.w
            + v1.x * v1.x + v1.y * v1.y + v1.z * v1.z + v1.w * v1.w
            + v2.x * v2.x + v2.y * v2.y + v2.z * v2.z + v2.w * v2.w;
#pragma unroll
    for (int off = 16; off > 0; off >>= 1)
        s += __shfl_xor_sync(0xffffffffu, s, off);

    const float inv = 1.0f / fmaxf(sqrtf(s), 1e-12f);

    float4* o = (float4*)(out + (size_t)b * 384);
    v0.x *= inv; v0.y *= inv; v0.z *= inv; v0.w *= inv;
    v1.x *= inv; v1.y *= inv; v1.z *= inv; v1.w *= inv;
    v2.x *= inv; v2.y *= inv; v2.z *= inv; v2.w *= inv;
    o[l]      = v0;
    o[l + 32] = v1;
    o[l + 64] = v2;
}

// ---------------------------------------------------------------------------
extern "C" void kernel_launch(void* const* d_in, const int* in_sizes, int n_in,
                              void* d_out, int out_size) {
    const float* emb    = (const float*)d_in[0];
    const float* Wa_adj = (const float*)d_in[1];
    const float* ba_adj = (const float*)d_in[2];
    const float* Wa_dis = (const float*)d_in[3];
    const float* ba_dis = (const float*)d_in[4];
    const float* W_self = (const float*)d_in[5];
    const float* W_adj  = (const float*)d_in[6];
    const float* W_dis  = (const float*)d_in[7];
    const float* WC     = (const float*)d_in[8];
    const float* bWC    = (const float*)d_in[9];
    const float* bias   = (const float*)d_in[10];
    const int* uid      = (const int*)d_in[11];
    const int* adj      = (const int*)d_in[12];
    const int* dis      = (const int*)d_in[13];
    const int* nidx     = (const int*)d_in[14];
    float* out          = (float*)d_out;

    cudaFuncSetAttribute(gemm_hmma_kernel,
                         cudaFuncAttributeMaxDynamicSharedMemorySize, GSM_TOT);

    fold_gather_kernel<<<FOLD_BLOCKS + U_NODES, 128>>>(
        emb, uid, adj, dis,
        Wa_adj, ba_adj, Wa_dis, ba_dis,
        W_self, W_adj, W_dis, WC, bWC, bias);
    gemm_hmma_kernel<<<dim3(3, 128), 512, GSM_TOT>>>();
    norm_gather_kernel<<<B_OUT / 8, 256>>>(nidx, out);
}